// round 1
// baseline (speedup 1.0000x reference)
#include <cuda_runtime.h>

// Problem geometry (fixed by reference: A is [16384, 512] fp32, row-major).
#define D      512          // feature dim (columns)
#define D4     128          // D / 4 (float4 chunks per row)
#define GRID   512          // pass1 blocks
#define TPB    512          // pass1 threads per block
#define ROWS_PER_ITER (GRID * 4)   // 4 row-phases per block

// Scratch (no allocations allowed -> __device__ globals).
__device__ float g_colsum[D];
__device__ float g_sumsq;

__global__ void ddc2_zero_kernel() {
    int t = threadIdx.x;
    if (t < D) g_colsum[t] = 0.0f;
    if (t == 0) g_sumsq = 0.0f;
}

// Pass 1: per-thread fp32 accumulation of column sums (float4 granularity)
// and sum of squares; smem combine across the 4 row-phases; atomicAdd of the
// 512-wide colsum (512 addrs x 512 blocks -> trivial L2 atomic load) and one
// sumsq atomic per block.
__global__ void __launch_bounds__(TPB, 2)
ddc2_pass1_kernel(const float* __restrict__ A, int n_rows) {
    const int t  = threadIdx.x;
    const int c4 = t & (D4 - 1);   // which float4 column chunk this thread owns
    const int rs = t >> 7;         // row phase 0..3 within the block

    const float4* __restrict__ A4 = reinterpret_cast<const float4*>(A);

    float ax = 0.f, ay = 0.f, az = 0.f, aw = 0.f;  // column partial sums
    float sq = 0.f;                                 // sum of squares partial

    int row = blockIdx.x * 4 + rs;
    #pragma unroll 8
    for (; row < n_rows; row += ROWS_PER_ITER) {
        float4 v = A4[(size_t)row * D4 + c4];
        ax += v.x; ay += v.y; az += v.z; aw += v.w;
        sq = fmaf(v.x, v.x, sq);
        sq = fmaf(v.y, v.y, sq);
        sq = fmaf(v.z, v.z, sq);
        sq = fmaf(v.w, v.w, sq);
    }

    // ---- combine the 4 row-phases for column sums via smem ----
    __shared__ float4 sc[4][D4];
    sc[rs][c4] = make_float4(ax, ay, az, aw);

    // ---- sumsq: warp shuffle reduce, then smem ----
    #pragma unroll
    for (int off = 16; off > 0; off >>= 1)
        sq += __shfl_xor_sync(0xFFFFFFFFu, sq, off);

    __shared__ float swarp[TPB / 32];
    if ((t & 31) == 0) swarp[t >> 5] = sq;
    __syncthreads();

    if (t < D4) {
        float4 s0 = sc[0][t];
        float4 s1 = sc[1][t];
        float4 s2 = sc[2][t];
        float4 s3 = sc[3][t];
        float cx = (s0.x + s1.x) + (s2.x + s3.x);
        float cy = (s0.y + s1.y) + (s2.y + s3.y);
        float cz = (s0.z + s1.z) + (s2.z + s3.z);
        float cw = (s0.w + s1.w) + (s2.w + s3.w);
        atomicAdd(&g_colsum[4 * t + 0], cx);
        atomicAdd(&g_colsum[4 * t + 1], cy);
        atomicAdd(&g_colsum[4 * t + 2], cz);
        atomicAdd(&g_colsum[4 * t + 3], cw);
    }

    if (t < TPB / 32) {
        float w = swarp[t];
        #pragma unroll
        for (int off = 8; off > 0; off >>= 1)
            w += __shfl_xor_sync(0xFFFFu, w, off);
        if (t == 0) atomicAdd(&g_sumsq, w);
    }
}

// Finalize: one block. dot(colsum, colsum) - sumsq, scaled by 1/(n*(n-1)).
__global__ void ddc2_finalize_kernel(float* __restrict__ out, int n_rows) {
    const int t = threadIdx.x;   // blockDim = 512
    float v = g_colsum[t];
    float p = v * v;

    #pragma unroll
    for (int off = 16; off > 0; off >>= 1)
        p += __shfl_xor_sync(0xFFFFFFFFu, p, off);

    __shared__ float swarp[16];
    if ((t & 31) == 0) swarp[t >> 5] = p;
    __syncthreads();

    if (t == 0) {
        float tot = 0.f;
        #pragma unroll
        for (int w = 0; w < 16; w++) tot += swarp[w];
        double denom = (double)n_rows * (double)(n_rows - 1);
        out[0] = (float)(((double)tot - (double)g_sumsq) / denom);
    }
}

extern "C" void kernel_launch(void* const* d_in, const int* in_sizes, int n_in,
                              void* d_out, int out_size) {
    const float* A = (const float*)d_in[0];
    const int n_rows = in_sizes[0] / D;      // 16384

    ddc2_zero_kernel<<<1, D>>>();
    ddc2_pass1_kernel<<<GRID, TPB>>>(A, n_rows);
    ddc2_finalize_kernel<<<1, D>>>((float*)d_out, n_rows);
}

// round 2
// speedup vs baseline: 1.5183x; 1.5183x over previous
#include <cuda_runtime.h>

// A is [16384, 512] fp32 row-major. Output = (||colsum||^2 - sum(A*A)) / (n*(n-1)).
#define D      512
#define D4     128                 // D/4 float4 chunks per row
#define GRID   256                 // single wave at occ 2 (<= 296 resident CTAs)
#define TPB    512
#define ROWS_PER_ITER (GRID * 4)   // 4 row-phases per block
#define FAST_ROWS 16384
#define FAST_ITERS (FAST_ROWS / ROWS_PER_ITER)   // 16, compile-time

// Persistent scratch (no allocs allowed). Zero at load; the LAST block of each
// launch re-zeroes after use, so every graph replay sees clean state.
__device__ float        g_colsum[D];
__device__ float        g_sumsq;
__device__ unsigned int g_count;

__global__ void __launch_bounds__(TPB, 2)
ddc2_fused_kernel(const float* __restrict__ A, int n_rows, float* __restrict__ out) {
    const int t  = threadIdx.x;
    const int c4 = t & (D4 - 1);     // float4 column chunk owned by this thread
    const int rs = t >> 7;           // row phase 0..3

    const float4* __restrict__ A4 = reinterpret_cast<const float4*>(A);

    float ax = 0.f, ay = 0.f, az = 0.f, aw = 0.f;   // column partial sums
    float sq = 0.f;                                  // sum-of-squares partial

    const size_t stride = (size_t)ROWS_PER_ITER * D4;
    size_t idx = (size_t)(blockIdx.x * 4 + rs) * D4 + c4;

    if (n_rows == FAST_ROWS) {
        // Fast path: exactly 16 iterations, unrolled in two MLP=8 batches.
        #pragma unroll
        for (int half = 0; half < 2; half++) {
            float4 v[8];
            #pragma unroll
            for (int i = 0; i < 8; i++)
                v[i] = A4[idx + (size_t)(half * 8 + i) * stride];
            #pragma unroll
            for (int i = 0; i < 8; i++) {
                ax += v[i].x; ay += v[i].y; az += v[i].z; aw += v[i].w;
                sq = fmaf(v[i].x, v[i].x, sq);
                sq = fmaf(v[i].y, v[i].y, sq);
                sq = fmaf(v[i].z, v[i].z, sq);
                sq = fmaf(v[i].w, v[i].w, sq);
            }
        }
    } else {
        // Generic fallback (unused for this problem's fixed shape).
        for (int row = blockIdx.x * 4 + rs; row < n_rows; row += ROWS_PER_ITER) {
            float4 v = A4[(size_t)row * D4 + c4];
            ax += v.x; ay += v.y; az += v.z; aw += v.w;
            sq = fmaf(v.x, v.x, sq);
            sq = fmaf(v.y, v.y, sq);
            sq = fmaf(v.z, v.z, sq);
            sq = fmaf(v.w, v.w, sq);
        }
    }

    // ---- intra-block combine of the 4 row-phases for colsum ----
    __shared__ float4 sc[4][D4];
    sc[rs][c4] = make_float4(ax, ay, az, aw);

    // ---- sumsq: warp shuffle reduce, stash per-warp ----
    #pragma unroll
    for (int off = 16; off > 0; off >>= 1)
        sq += __shfl_xor_sync(0xFFFFFFFFu, sq, off);

    __shared__ float swarp[TPB / 32];
    if ((t & 31) == 0) swarp[t >> 5] = sq;
    __syncthreads();

    if (t < D4) {
        float4 s0 = sc[0][t];
        float4 s1 = sc[1][t];
        float4 s2 = sc[2][t];
        float4 s3 = sc[3][t];
        atomicAdd(&g_colsum[4 * t + 0], (s0.x + s1.x) + (s2.x + s3.x));
        atomicAdd(&g_colsum[4 * t + 1], (s0.y + s1.y) + (s2.y + s3.y));
        atomicAdd(&g_colsum[4 * t + 2], (s0.z + s1.z) + (s2.z + s3.z));
        atomicAdd(&g_colsum[4 * t + 3], (s0.w + s1.w) + (s2.w + s3.w));
    }
    if (t < TPB / 32) {
        float w = swarp[t];
        #pragma unroll
        for (int off = 8; off > 0; off >>= 1)
            w += __shfl_xor_sync(0xFFFFu, w, off);
        if (t == 0) atomicAdd(&g_sumsq, w);
    }

    // ---- last-block-finishes: fence + counter ----
    __syncthreads();                 // all block atomics issued before the bump
    __shared__ int is_last;
    if (t == 0) {
        __threadfence();             // make this block's RED results visible
        unsigned prev = atomicAdd(&g_count, 1u);
        is_last = (prev == gridDim.x - 1u);
    }
    __syncthreads();

    if (is_last) {
        // All other blocks' atomics are globally visible (they fenced before
        // bumping the counter we observed at max).
        float v = g_colsum[t];       // TPB == D == 512
        float p = v * v;
        #pragma unroll
        for (int off = 16; off > 0; off >>= 1)
            p += __shfl_xor_sync(0xFFFFFFFFu, p, off);

        __shared__ float fwarp[TPB / 32];
        if ((t & 31) == 0) fwarp[t >> 5] = p;
        __syncthreads();

        if (t == 0) {
            float tot = 0.f;
            #pragma unroll
            for (int w = 0; w < TPB / 32; w++) tot += fwarp[w];
            double denom = (double)n_rows * (double)(n_rows - 1);
            out[0] = (float)(((double)tot - (double)g_sumsq) / denom);
            // reset scalars for the next graph replay
            g_sumsq = 0.f;
            g_count = 0u;
        }
        g_colsum[t] = 0.f;           // reset vector for the next replay
    }
}

extern "C" void kernel_launch(void* const* d_in, const int* in_sizes, int n_in,
                              void* d_out, int out_size) {
    const float* A = (const float*)d_in[0];
    const int n_rows = in_sizes[0] / D;   // 16384
    ddc2_fused_kernel<<<GRID, TPB>>>(A, n_rows, (float*)d_out);
}